// round 7
// baseline (speedup 1.0000x reference)
#include <cuda_runtime.h>
#include <cstdint>

// VoxelHashTable — counting-sort-clustered gather, minimal pre-pass.
// Gather is at its roofline: ~514MB deduped feature reads + 805MB writes at
// the measured ~6.6TB/s ceiling. Pre-pass (hash+scan+scatter) trimmed:
//   - no zero_hist kernel: globals start zeroed; scan_hist re-zeroes g_hist
//     after reading it, so every graph replay sees a clean histogram
//   - scatter: 1 query/thread, 1024 blocks (was occ=19%, latency-bound)
//   - rank-within-bin captured from hash_hist's atomicAdd -> scatter atomic-free

#define FEATURE_DIM 768
#define VEC4_PER_ROW (FEATURE_DIM / 4)     // 192
#define V4_PER_LANE (VEC4_PER_ROW / 32)    // 6
#define TABLE_MASK ((1u << 20) - 1u)
#define THREADS 256
#define M_MAX (1 << 18)                    // 262144 queries
#define BUCKET_SHIFT 7                     // 128 voxel rows per bucket
#define NBINS 8192

__device__ int g_vidx[M_MAX];
__device__ int g_rank[M_MAX];
__device__ int g_perm[M_MAX];
__device__ int g_hist[NBINS];              // zero-init at load; scan re-zeroes
__device__ int g_off[NBINS];

// 4 queries per thread: hash, table lookup, bin rank via atomicAdd return.
__global__ void __launch_bounds__(256) hash_hist(
    const float* __restrict__ query_pts,   // [M, 3]
    const int* __restrict__ buf,           // [2^20], int32
    int total_voxels)
{
    const int t   = blockIdx.x * blockDim.x + threadIdx.x;
    const int qi0 = t * 4;

    // 4 points = 12 floats = 3 aligned float4 loads (qi0 % 4 == 0).
    const float4* qp = (const float4*)(query_pts + qi0 * 3);
    const float4 a = __ldg(qp + 0);
    const float4 b = __ldg(qp + 1);
    const float4 c = __ldg(qp + 2);
    const float px[4] = {a.x, a.w, b.z, c.y};
    const float py[4] = {a.y, b.x, b.w, c.z};
    const float pz[4] = {a.z, b.y, c.x, c.w};

    unsigned h[4];
    #pragma unroll
    for (int i = 0; i < 4; i++) {
        // f32 division by 0.1f required for bit-exact floor(q / RES).
        const long long gx = (long long)floorf(px[i] / 0.1f);
        const long long gy = (long long)floorf(py[i] / 0.1f);
        const long long gz = (long long)floorf(pz[i] / 0.1f);
        // Products ~1e10 overflow int32 -> 64-bit. Pow2 mod == AND (neg-safe).
        h[i] = (unsigned)((gx * 73856093LL + gy * 19349669LL
                           + gz * 83492791LL) & (long long)TABLE_MASK);
    }

    int v[4];
    #pragma unroll
    for (int i = 0; i < 4; i++)            // 4 independent table loads
        v[i] = __ldg(&buf[h[i]]);

    int4 vv, rr;
    int* vp = &vv.x;
    int* rp = &rr.x;
    #pragma unroll
    for (int i = 0; i < 4; i++) {
        int vi = (v[i] < total_voxels) ? v[i] : -1;
        const int bin = (vi >= 0) ? (vi >> BUCKET_SHIFT) : (NBINS - 1);
        vp[i] = vi;
        rp[i] = atomicAdd(&g_hist[bin], 1);   // rank within bin
    }

    *(int4*)(g_vidx + qi0) = vv;
    *(int4*)(g_rank + qi0) = rr;
}

// Exclusive prefix sum over NBINS=8192 bins -> g_off. Single 1024-thread
// block. Also re-zeroes g_hist so the next graph replay starts clean.
__global__ void __launch_bounds__(1024) scan_hist()
{
    const int tid  = threadIdx.x;
    const int lane = tid & 31;
    const int warp = tid >> 5;

    int v[NBINS / 1024];
    int sum = 0;
    #pragma unroll
    for (int i = 0; i < NBINS / 1024; i++) {
        v[i] = g_hist[tid * (NBINS / 1024) + i];
        g_hist[tid * (NBINS / 1024) + i] = 0;   // reset for next replay
        sum += v[i];
    }

    int x = sum;
    #pragma unroll
    for (int d = 1; d < 32; d <<= 1) {
        int y = __shfl_up_sync(0xFFFFFFFFu, x, d);
        if (lane >= d) x += y;
    }

    __shared__ int wsum[32];
    if (lane == 31) wsum[warp] = x;
    __syncthreads();
    if (warp == 0) {
        int w = wsum[lane];
        #pragma unroll
        for (int d = 1; d < 32; d <<= 1) {
            int y = __shfl_up_sync(0xFFFFFFFFu, w, d);
            if (lane >= d) w += y;
        }
        wsum[lane] = w;
    }
    __syncthreads();

    int excl = x - sum + (warp > 0 ? wsum[warp - 1] : 0);
    #pragma unroll
    for (int i = 0; i < NBINS / 1024; i++) {
        g_off[tid * (NBINS / 1024) + i] = excl;
        excl += v[i];
    }
}

// Atomic-free scatter: pos = off[bin] + rank. 1 query/thread (occupancy was
// the limiter at 4/thread: 256 blocks -> occ 19%, pure latency exposure).
__global__ void __launch_bounds__(256) scatter_perm()
{
    const int qi = blockIdx.x * blockDim.x + threadIdx.x;

    const int v = g_vidx[qi];
    const int r = g_rank[qi];
    const int bin = (v >= 0) ? (v >> BUCKET_SHIFT) : (NBINS - 1);
    const int pos = __ldg(&g_off[bin]) + r;   // off[] is L2-resident
    g_perm[pos] = qi;
}

__global__ void __launch_bounds__(THREADS) gather_phase(
    const float4* __restrict__ voxel_features,  // [total_voxels, 192] as float4
    float4* __restrict__ out)                   // [M, 192] as float4
{
    const int warp = threadIdx.x >> 5;
    const int lane = threadIdx.x & 31;
    const int wi   = blockIdx.x * (THREADS / 32) + warp;

    const int qi = __ldg(&g_perm[wi]);   // L2-resident, warp-broadcast
    const int v  = __ldg(&g_vidx[qi]);

    const float4* src = voxel_features + (size_t)v * VEC4_PER_ROW + lane;
    float4*       dst = out            + (size_t)qi * VEC4_PER_ROW + lane;

    float4 r[V4_PER_LANE];
    if (v >= 0) {
        #pragma unroll
        for (int i = 0; i < V4_PER_LANE; i++)   // 6 loads in flight (MLP=6)
            r[i] = __ldg(src + 32 * i);
    } else {
        #pragma unroll
        for (int i = 0; i < V4_PER_LANE; i++)
            r[i] = make_float4(0.f, 0.f, 0.f, 0.f);
    }

    // Streaming stores: output never re-read; keep L2 for feature rows.
    #pragma unroll
    for (int i = 0; i < V4_PER_LANE; i++)
        __stcs(dst + 32 * i, r[i]);
}

extern "C" void kernel_launch(void* const* d_in, const int* in_sizes, int n_in,
                              void* d_out, int out_size)
{
    const float*  query_pts = (const float*)d_in[0];
    const float4* feats     = (const float4*)d_in[1];
    const int*    buf       = (const int*)d_in[2];
    float4*       out       = (float4*)d_out;

    const int M = in_sizes[0] / 3;                  // 262144
    const int total_voxels = in_sizes[1] / FEATURE_DIM;

    hash_hist<<<M / (256 * 4), 256>>>(query_pts, buf, total_voxels);
    scan_hist<<<1, 1024>>>();
    scatter_perm<<<M / 256, 256>>>();

    gather_phase<<<M / (THREADS / 32), THREADS>>>(feats, out);
}

// round 8
// speedup vs baseline: 1.0043x; 1.0043x over previous
#include <cuda_runtime.h>
#include <cstdint>

// VoxelHashTable — counting-sort-clustered gather.
// gather_phase measured at its roofline (183.7us, 6.5TB/s, reads deduped by
// vidx-clustering). All remaining slack is the pre-pass; this round fixes
// hash_hist's occupancy (was 256 blocks / 4 queries per thread -> ~450
// threads/SM, latency-bound on the query->hash->table->atomic chain).
//
//   1. hash_hist: 1 query/thread; rank-within-bin from atomicAdd return
//   2. scan_hist: 8192-bin exclusive scan, one block; re-zeroes g_hist
//   3. scatter_perm: atomic-free, pos = off[bin] + rank
//   4. gather_phase: warp-per-row, 6 independent float4 loads, __stcs stores

#define FEATURE_DIM 768
#define VEC4_PER_ROW (FEATURE_DIM / 4)     // 192
#define V4_PER_LANE (VEC4_PER_ROW / 32)    // 6
#define TABLE_MASK ((1u << 20) - 1u)
#define THREADS 256
#define M_MAX (1 << 18)                    // 262144 queries
#define BUCKET_SHIFT 7                     // 128 voxel rows per bucket
#define NBINS 8192

__device__ int g_vidx[M_MAX];
__device__ int g_rank[M_MAX];
__device__ int g_perm[M_MAX];
__device__ int g_hist[NBINS];              // zero-init at load; scan re-zeroes
__device__ int g_off[NBINS];

// 1 query/thread: hash, table lookup, bin rank via atomicAdd return.
__global__ void __launch_bounds__(256) hash_hist(
    const float* __restrict__ query_pts,   // [M, 3]
    const int* __restrict__ buf,           // [2^20], int32
    int total_voxels)
{
    const int qi = blockIdx.x * blockDim.x + threadIdx.x;

    const float px = __ldg(&query_pts[qi * 3 + 0]);
    const float py = __ldg(&query_pts[qi * 3 + 1]);
    const float pz = __ldg(&query_pts[qi * 3 + 2]);

    // f32 division by 0.1f required for bit-exact floor(q / RES).
    const long long gx = (long long)floorf(px / 0.1f);
    const long long gy = (long long)floorf(py / 0.1f);
    const long long gz = (long long)floorf(pz / 0.1f);

    // Products ~1e10 overflow int32 -> 64-bit. Pow2 mod == AND (neg-safe).
    const unsigned h = (unsigned)((gx * 73856093LL + gy * 19349669LL
                                   + gz * 83492791LL) & (long long)TABLE_MASK);

    int v = __ldg(&buf[h]);
    if (v >= total_voxels) v = -1;

    const int bin = (v >= 0) ? (v >> BUCKET_SHIFT) : (NBINS - 1);
    g_vidx[qi] = v;
    g_rank[qi] = atomicAdd(&g_hist[bin], 1);   // rank within bin
}

// Exclusive prefix sum over NBINS=8192 bins -> g_off. Single 1024-thread
// block. Also re-zeroes g_hist so the next graph replay starts clean.
__global__ void __launch_bounds__(1024) scan_hist()
{
    const int tid  = threadIdx.x;
    const int lane = tid & 31;
    const int warp = tid >> 5;

    int v[NBINS / 1024];
    int sum = 0;
    #pragma unroll
    for (int i = 0; i < NBINS / 1024; i++) {
        v[i] = g_hist[tid * (NBINS / 1024) + i];
        g_hist[tid * (NBINS / 1024) + i] = 0;   // reset for next replay
        sum += v[i];
    }

    int x = sum;
    #pragma unroll
    for (int d = 1; d < 32; d <<= 1) {
        int y = __shfl_up_sync(0xFFFFFFFFu, x, d);
        if (lane >= d) x += y;
    }

    __shared__ int wsum[32];
    if (lane == 31) wsum[warp] = x;
    __syncthreads();
    if (warp == 0) {
        int w = wsum[lane];
        #pragma unroll
        for (int d = 1; d < 32; d <<= 1) {
            int y = __shfl_up_sync(0xFFFFFFFFu, w, d);
            if (lane >= d) w += y;
        }
        wsum[lane] = w;
    }
    __syncthreads();

    int excl = x - sum + (warp > 0 ? wsum[warp - 1] : 0);
    #pragma unroll
    for (int i = 0; i < NBINS / 1024; i++) {
        g_off[tid * (NBINS / 1024) + i] = excl;
        excl += v[i];
    }
}

// Atomic-free scatter: pos = off[bin] + rank. 1 query/thread.
__global__ void __launch_bounds__(256) scatter_perm()
{
    const int qi = blockIdx.x * blockDim.x + threadIdx.x;

    const int v = g_vidx[qi];
    const int r = g_rank[qi];
    const int bin = (v >= 0) ? (v >> BUCKET_SHIFT) : (NBINS - 1);
    const int pos = __ldg(&g_off[bin]) + r;   // off[] is L2-resident
    g_perm[pos] = qi;
}

__global__ void __launch_bounds__(THREADS) gather_phase(
    const float4* __restrict__ voxel_features,  // [total_voxels, 192] as float4
    float4* __restrict__ out)                   // [M, 192] as float4
{
    const int warp = threadIdx.x >> 5;
    const int lane = threadIdx.x & 31;
    const int wi   = blockIdx.x * (THREADS / 32) + warp;

    const int qi = __ldg(&g_perm[wi]);   // L2-resident, warp-broadcast
    const int v  = __ldg(&g_vidx[qi]);

    const float4* src = voxel_features + (size_t)v * VEC4_PER_ROW + lane;
    float4*       dst = out            + (size_t)qi * VEC4_PER_ROW + lane;

    float4 r[V4_PER_LANE];
    if (v >= 0) {
        #pragma unroll
        for (int i = 0; i < V4_PER_LANE; i++)   // 6 loads in flight (MLP=6)
            r[i] = __ldg(src + 32 * i);
    } else {
        #pragma unroll
        for (int i = 0; i < V4_PER_LANE; i++)
            r[i] = make_float4(0.f, 0.f, 0.f, 0.f);
    }

    // Streaming stores: output never re-read; keep L2 for feature rows.
    #pragma unroll
    for (int i = 0; i < V4_PER_LANE; i++)
        __stcs(dst + 32 * i, r[i]);
}

extern "C" void kernel_launch(void* const* d_in, const int* in_sizes, int n_in,
                              void* d_out, int out_size)
{
    const float*  query_pts = (const float*)d_in[0];
    const float4* feats     = (const float4*)d_in[1];
    const int*    buf       = (const int*)d_in[2];
    float4*       out       = (float4*)d_out;

    const int M = in_sizes[0] / 3;                  // 262144
    const int total_voxels = in_sizes[1] / FEATURE_DIM;

    hash_hist<<<M / 256, 256>>>(query_pts, buf, total_voxels);
    scan_hist<<<1, 1024>>>();
    scatter_perm<<<M / 256, 256>>>();

    gather_phase<<<M / (THREADS / 32), THREADS>>>(feats, out);
}